// round 7
// baseline (speedup 1.0000x reference)
#include <cuda_runtime.h>
#include <math.h>

// ---------------------------------------------------------------------------
// RoutingStorage (GR4J routing). Chunk-parallel scan with warmup.
// R7: wall-time law discovered: wall = iterations x ~157cyc, independent of
// chains/thread -> per-step cost is in-order-issue exposure of a serially
// emitted step body, not the 47-cyc dataflow chain. Fix: FOUR chains per
// thread written STAGE-BY-STAGE (program order alternates chains every
// instruction, covering all latencies by construction) + cross-iteration
// register prefetch of conv inputs. W=256 for accuracy margin.
// ---------------------------------------------------------------------------

#define T_MAX 262144
constexpr int K       = 4;     // chains per thread
constexpr int CHUNK_L = 32;    // output steps per chain
constexpr int WARMUP  = 256;   // warmup steps
constexpr int ITERS   = WARMUP + CHUNK_L;              // 288
constexpr int BLK     = 32;    // threads per block
constexpr int CPB     = BLK * K;                       // 128 chains/block
constexpr int OSZ     = CPB * CHUNK_L;                 // 4096 outputs/block
constexpr int WSZ     = (CPB - 1) * CHUNK_L + ITERS;   // 4352 window
constexpr int WSZP    = WSZ + WSZ / 32;                // padded
constexpr int OSZP    = OSZ + OSZ / 32;
#define PAD 16

// Front-padded with WARMUP zeros: index pi corresponds to t = pi - WARMUP.
static __device__ float g_c1[WARMUP + T_MAX + PAD];
static __device__ float g_c2[WARMUP + T_MAX + PAD];

__device__ __forceinline__ float fsqrt_approx(float x) {
    float y; asm("sqrt.approx.f32 %0, %1;" : "=f"(y) : "f"(x)); return y;
}

// Unit-hydrograph ordinates for X4 = 2.5:
__constant__ float c_o1[3] = {0.10119288512538814f, 0.47124051711455807f,
                              0.42756659776005380f};
__constant__ float c_o2[6] = {0.05059644256269407f, 0.23562025855727903f,
                              0.42756659776005380f, 0.23562025855727903f,
                              0.05059644256269407f, 0.0f};

__global__ void conv_kernel(const float* __restrict__ x, int T) {
    int i = blockIdx.x * blockDim.x + threadIdx.x;
    if (i >= WARMUP + T + PAD) return;
    int t = i - WARMUP;
    if (t < 0 || t >= T) { g_c1[i] = 0.0f; g_c2[i] = 0.0f; return; }
    float c1 = 0.0f, c2 = 0.0f;
#pragma unroll
    for (int j = 0; j < 6; ++j) {
        int idx = t - j;
        if (idx >= 0) {
            float4 row = *reinterpret_cast<const float4*>(x + 4 * idx);
            float pr = row.w + (row.x - row.z);   // perc + (p_n - p_s)
            if (j < 3) c1 += c_o1[j] * (0.9f * pr);
            c2 += c_o2[j] * (0.1f * pr);
        }
    }
    g_c1[i] = c1; g_c2[i] = c2;
}

// (1+u)^(-1/4) deg-4 Horner
#define P1 (-0.25f)
#define P2 ( 0.15625f)
#define P3 (-0.1171875f)
#define P4 ( 0.0952148438f)
// (1+u)^(-7/8) deg-3 Horner (off-critical gw branch)
#define Q1 (-0.875f)
#define Q2 ( 0.8203125f)
#define Q3 (-0.7861328125f)

__device__ __forceinline__ int padi(int d) { return d + (d >> 5); }

__global__ void __launch_bounds__(BLK, 1)
scan_kernel(const float* __restrict__ x2p,
            const float* __restrict__ x3p,
            float* __restrict__ out, int T) {
    extern __shared__ float dsm[];
    float* s1 = dsm;                       // [WSZP]
    float* s2 = dsm + WSZP;                // [WSZP]
    float* sq = dsm + 2 * WSZP;            // [OSZP]
    float* sr = dsm + 2 * WSZP + OSZP;     // [OSZP]

    int tid = threadIdx.x;
    int t0b = blockIdx.x * OSZ;
    if (t0b >= T) return;

    // ---- Stage conv window: coalesced global -> padded smem ----
    {
        const float* g1 = g_c1 + t0b;
        const float* g2 = g_c2 + t0b;
        for (int d = tid; d < WSZ; d += BLK) {
            s1[padi(d)] = g1[d];
            s2[padi(d)] = g2[d];
        }
    }
    __syncthreads();

    const float x2  = __ldg(x2p);
    const float x3  = __ldg(x3p);
    const float inv = 1.0f / x3;
    float inv2 = inv * inv, inv4 = inv2 * inv2;
    const float kx  = __powf(x2, 0.2857142857f) * inv;   // x2^(2/7)/x3

    // Chain j of this thread is global chain c = tid + 32*j; it reads smem
    // window index d = 32*c + i = 32*tid + 1024*j + i.
    const int b0 = tid * CHUNK_L;

    float z[K], gw[K];                 // z = r + gw (carried), gw separate for q_d
#pragma unroll
    for (int j = 0; j < K; ++j) { z[j] = 0.0f; gw[j] = 0.0f; }

    float c1c[K], c1n[K];
#pragma unroll
    for (int j = 0; j < K; ++j) c1c[j] = s1[padi(b0 + 1024 * j)];

    // ---- Warmup: stage-ordered across 4 chains, prefetched inputs ----
    for (int i = 0; i < WARMUP; ++i) {
#pragma unroll
        for (int j = 0; j < K; ++j) c1n[j] = s1[padi(b0 + 1024 * j + i + 1)];
        float s[K], u[K], p[K], qq[K], v[K], sv[K], gs[K], rn[K];
#pragma unroll
        for (int j = 0; j < K; ++j) s[j] = fmaxf(z[j] + c1c[j], 0.0f);
#pragma unroll
        for (int j = 0; j < K; ++j) v[j] = s[j] * kx;
#pragma unroll
        for (int j = 0; j < K; ++j) sv[j] = fsqrt_approx(v[j]);
#pragma unroll
        for (int j = 0; j < K; ++j) { float a = s[j] * s[j]; u[j] = (a * inv4) * a; }
#pragma unroll
        for (int j = 0; j < K; ++j) p[j] = fmaf(u[j], P4, P3);
#pragma unroll
        for (int j = 0; j < K; ++j) p[j] = fmaf(u[j], p[j], P2);
#pragma unroll
        for (int j = 0; j < K; ++j) p[j] = fmaf(u[j], p[j], P1);
#pragma unroll
        for (int j = 0; j < K; ++j) p[j] = fmaf(u[j], p[j], 1.0f);
#pragma unroll
        for (int j = 0; j < K; ++j) qq[j] = fmaf(u[j], Q3, Q2);
#pragma unroll
        for (int j = 0; j < K; ++j) qq[j] = fmaf(u[j], qq[j], Q1);
#pragma unroll
        for (int j = 0; j < K; ++j) qq[j] = fmaf(u[j], qq[j], 1.0f);
#pragma unroll
        for (int j = 0; j < K; ++j) { float v2 = v[j] * v[j]; gs[j] = (v2 * v[j]) * sv[j]; }
#pragma unroll
        for (int j = 0; j < K; ++j) rn[j] = s[j] * p[j];
#pragma unroll
        for (int j = 0; j < K; ++j) gw[j] = gs[j] * qq[j];
#pragma unroll
        for (int j = 0; j < K; ++j) z[j] = rn[j] + gw[j];
#pragma unroll
        for (int j = 0; j < K; ++j) c1c[j] = c1n[j];
    }

    // ---- Output phase: same stages + q_d/q/r staging to smem ----
    for (int i = WARMUP; i < ITERS; ++i) {
        int jj = i - WARMUP;
        float c2c[K];
#pragma unroll
        for (int j = 0; j < K; ++j) c2c[j] = s2[padi(b0 + 1024 * j + i)];
#pragma unroll
        for (int j = 0; j < K; ++j) c1n[j] = (i + 1 < ITERS)
                                   ? s1[padi(b0 + 1024 * j + i + 1)] : 0.0f;
        float s[K], u[K], p[K], qq[K], v[K], sv[K], gs[K], rn[K], qd[K];
#pragma unroll
        for (int j = 0; j < K; ++j) qd[j] = fmaxf(c2c[j] + gw[j], 0.0f);  // uses OLD gw
#pragma unroll
        for (int j = 0; j < K; ++j) s[j] = fmaxf(z[j] + c1c[j], 0.0f);
#pragma unroll
        for (int j = 0; j < K; ++j) v[j] = s[j] * kx;
#pragma unroll
        for (int j = 0; j < K; ++j) sv[j] = fsqrt_approx(v[j]);
#pragma unroll
        for (int j = 0; j < K; ++j) { float a = s[j] * s[j]; u[j] = (a * inv4) * a; }
#pragma unroll
        for (int j = 0; j < K; ++j) p[j] = fmaf(u[j], P4, P3);
#pragma unroll
        for (int j = 0; j < K; ++j) p[j] = fmaf(u[j], p[j], P2);
#pragma unroll
        for (int j = 0; j < K; ++j) p[j] = fmaf(u[j], p[j], P1);
#pragma unroll
        for (int j = 0; j < K; ++j) p[j] = fmaf(u[j], p[j], 1.0f);
#pragma unroll
        for (int j = 0; j < K; ++j) qq[j] = fmaf(u[j], Q3, Q2);
#pragma unroll
        for (int j = 0; j < K; ++j) qq[j] = fmaf(u[j], qq[j], Q1);
#pragma unroll
        for (int j = 0; j < K; ++j) qq[j] = fmaf(u[j], qq[j], 1.0f);
#pragma unroll
        for (int j = 0; j < K; ++j) { float v2 = v[j] * v[j]; gs[j] = (v2 * v[j]) * sv[j]; }
#pragma unroll
        for (int j = 0; j < K; ++j) rn[j] = s[j] * p[j];
#pragma unroll
        for (int j = 0; j < K; ++j) {
            int od = b0 + 1024 * j + jj;        // = 32*c + jj
            sq[padi(od)] = (s[j] - rn[j]) + qd[j];
            sr[padi(od)] = rn[j];
        }
#pragma unroll
        for (int j = 0; j < K; ++j) gw[j] = gs[j] * qq[j];
#pragma unroll
        for (int j = 0; j < K; ++j) z[j] = rn[j] + gw[j];
#pragma unroll
        for (int j = 0; j < K; ++j) c1c[j] = c1n[j];
    }
    __syncthreads();

    // ---- Coalesced epilogue ----
    float* __restrict__ qout = out;        // qsim    [0, T)
    float* __restrict__ rout = out + T;    // r_store [T, 2T)
    int lim = T - t0b; if (lim > OSZ) lim = OSZ;
    for (int d = tid; d < lim; d += BLK) {
        qout[t0b + d] = sq[padi(d)];
        rout[t0b + d] = sr[padi(d)];
    }
}

extern "C" void kernel_launch(void* const* d_in, const int* in_sizes, int n_in,
                              void* d_out, int out_size) {
    const float* x  = (const float*)d_in[0];
    const float* x2 = (const float*)d_in[1];
    const float* x3 = (const float*)d_in[2];
    int T = in_sizes[0] / 4;
    if (T > T_MAX) T = T_MAX;

    int N = WARMUP + T + PAD;
    conv_kernel<<<(N + 255) / 256, 256>>>(x, T);

    const int smem_bytes = (2 * WSZP + 2 * OSZP) * sizeof(float);  // ~70 KB
    cudaFuncSetAttribute(scan_kernel,
                         cudaFuncAttributeMaxDynamicSharedMemorySize, smem_bytes);
    int nblocks = (T + OSZ - 1) / OSZ;     // 64 for T = 262144
    scan_kernel<<<nblocks, BLK, smem_bytes>>>(x2, x3, (float*)d_out, T);
}